// round 3
// baseline (speedup 1.0000x reference)
#include <cuda_runtime.h>
#include <cuda_bf16.h>
#include <math.h>

// Problem constants
#define HH 256
#define NN 50000
#define LN_EPS 1e-5f

// ---------------- scratch (no allocations allowed) ----------------
__device__ float g_msg1[(size_t)NN * HH];
__device__ float g_msg2[(size_t)NN * HH];
__device__ float g_agg [(size_t)NN * HH];
__device__ float g_cnt [NN];
__device__ float g_comb[(size_t)NN * 2 * HH];
__device__ float g_c1  [(size_t)NN * HH];
__device__ float g_c2  [(size_t)NN * HH];
__device__ int   g_idx_is64;

__device__ __forceinline__ float gelu_exact(float x) {
    return 0.5f * x * (1.0f + erff(x * 0.7071067811865476f));
}

// ---------------- index-dtype detection ----------------
// int64 indices are all in [0, N). If the buffer actually holds int32,
// an int64 read packs two random int32s -> value far outside [0, N).
__global__ void detect_idx_kernel(const void* __restrict__ ei, int E, int N)
{
    if (blockIdx.x != 0 || threadIdx.x != 0) return;
    const long long* p = (const long long*)ei;
    int n = E < 64 ? E : 64;
    int ok = 1;
    for (int i = 0; i < n; i++) {
        long long v = p[i];
        if (v < 0 || v >= (long long)N) { ok = 0; break; }
    }
    g_idx_is64 = ok;
}

// ---------------- tiled SGEMM + bias + GELU ----------------
// C[M,N] = gelu(A[M,K] @ B[K,N] + bias[N]); row-major everywhere.
// 128x128 tile, BK=8, 256 threads, 8x8 per-thread microtile.
#define BM 128
#define BN 128
#define BK 8
#define TM 8
#define TN 8

__global__ void __launch_bounds__(256)
sgemm_bias_gelu(const float* __restrict__ A, const float* __restrict__ B,
                const float* __restrict__ bias, float* __restrict__ C,
                int M, int N, int K)
{
    __shared__ float As[BK][BM + 4];
    __shared__ float Bs[BK][BN + 4];

    const int tid = threadIdx.x;
    const int tx = tid & 15;        // 0..15  (N direction)
    const int ty = tid >> 4;        // 0..15  (M direction)
    const int bx = blockIdx.x;      // N tile
    const int by = blockIdx.y;      // M tile
    const int gm = by * BM;

    const int a_row = tid >> 1;           // 0..127
    const int a_col = (tid & 1) * 4;      // 0 or 4
    const int b_row = tid >> 5;           // 0..7
    const int b_col = (tid & 31) * 4;     // 0..124

    const float* Ab = A + (long long)gm * K;
    const float* Bb = B + bx * BN;

    float acc[TM][TN];
    #pragma unroll
    for (int i = 0; i < TM; i++)
        #pragma unroll
        for (int j = 0; j < TN; j++) acc[i][j] = 0.0f;

    for (int kt = 0; kt < K; kt += BK) {
        float4 av = make_float4(0.f, 0.f, 0.f, 0.f);
        if (gm + a_row < M)
            av = *(const float4*)(Ab + (long long)a_row * K + kt + a_col);
        As[a_col + 0][a_row] = av.x;
        As[a_col + 1][a_row] = av.y;
        As[a_col + 2][a_row] = av.z;
        As[a_col + 3][a_row] = av.w;

        float4 bv = *(const float4*)(Bb + (long long)(kt + b_row) * N + b_col);
        *(float4*)&Bs[b_row][b_col] = bv;

        __syncthreads();

        #pragma unroll
        for (int k = 0; k < BK; k++) {
            float ar[TM], br[TN];
            #pragma unroll
            for (int i = 0; i < TM; i++) ar[i] = As[k][ty * TM + i];
            #pragma unroll
            for (int j = 0; j < TN; j++) br[j] = Bs[k][tx * TN + j];
            #pragma unroll
            for (int i = 0; i < TM; i++)
                #pragma unroll
                for (int j = 0; j < TN; j++)
                    acc[i][j] = fmaf(ar[i], br[j], acc[i][j]);
        }
        __syncthreads();
    }

    #pragma unroll
    for (int i = 0; i < TM; i++) {
        const int row = gm + ty * TM + i;
        if (row >= M) continue;
        #pragma unroll
        for (int j = 0; j < TN; j += 4) {
            const int col = bx * BN + tx * TN + j;
            float4 v;
            v.x = gelu_exact(acc[i][j + 0] + bias[col + 0]);
            v.y = gelu_exact(acc[i][j + 1] + bias[col + 1]);
            v.z = gelu_exact(acc[i][j + 2] + bias[col + 2]);
            v.w = gelu_exact(acc[i][j + 3] + bias[col + 3]);
            *(float4*)(C + (long long)row * N + col) = v;
        }
    }
}

// ---------------- zero agg + counts ----------------
__global__ void zero_kernel(float* __restrict__ agg, float* __restrict__ cnt, int M)
{
    long long i = (long long)blockIdx.x * blockDim.x + threadIdx.x;
    long long n4 = (long long)M * HH / 4;
    if (i < n4) {
        ((float4*)agg)[i] = make_float4(0.f, 0.f, 0.f, 0.f);
    } else if (i < n4 + M) {
        cnt[i - n4] = 0.f;
    }
}

// ---------------- per-edge scatter: agg[dst] += msg[src], cnt[dst] += 1 ----------------
// one warp per edge; 64 float4 per row -> 2 float4 per lane
__global__ void __launch_bounds__(256)
scatter_kernel(const float* __restrict__ msg, const void* __restrict__ ei_raw,
               float* __restrict__ agg, float* __restrict__ cnt, int E)
{
    int warp = (int)((blockIdx.x * (long long)blockDim.x + threadIdx.x) >> 5);
    int lane = threadIdx.x & 31;
    if (warp >= E) return;

    long long src, dst;
    if (g_idx_is64) {
        const long long* p = (const long long*)ei_raw;
        src = p[warp];
        dst = p[(long long)E + warp];
    } else {
        const int* p = (const int*)ei_raw;
        src = p[warp];
        dst = p[E + warp];
    }

    const float4* s = (const float4*)(msg + src * HH);
    float4*       d = (float4*)(agg + dst * HH);
    #pragma unroll
    for (int i = 0; i < 2; i++) {
        float4 v = __ldg(s + lane + 32 * i);
        atomicAdd(d + lane + 32 * i, v);   // vector red (sm_90+)
    }
    if (lane == 0) atomicAdd(cnt + dst, 1.0f);
}

// ---------------- build combined = [target || agg / max(cnt,1)] ----------------
__global__ void combine_kernel(const float* __restrict__ target,
                               const float* __restrict__ agg,
                               const float* __restrict__ cnt,
                               float* __restrict__ comb, int M)
{
    long long i = (long long)blockIdx.x * blockDim.x + threadIdx.x;
    long long total = (long long)M * HH / 4;
    if (i >= total) return;
    int row = (int)(i / (HH / 4));
    int c4  = (int)(i % (HH / 4));
    float4 t = ((const float4*)target)[i];
    float inv = 1.0f / fmaxf(cnt[row], 1.0f);
    float4 a = ((const float4*)agg)[i];
    a.x *= inv; a.y *= inv; a.z *= inv; a.w *= inv;
    float4* out = (float4*)(comb + (long long)row * 2 * HH);
    out[c4] = t;
    out[HH / 4 + c4] = a;
}

// ---------------- residual + layernorm ----------------
__global__ void __launch_bounds__(256)
ln_kernel(const float* __restrict__ c2, const float* __restrict__ target,
          const float* __restrict__ gamma, const float* __restrict__ beta,
          float* __restrict__ out, int M)
{
    int row = blockIdx.x;
    if (row >= M) return;
    int t = threadIdx.x;
    int lane = t & 31, wid = t >> 5;

    float x = c2[(long long)row * HH + t] + target[(long long)row * HH + t];
    float s1 = x, s2 = x * x;
    #pragma unroll
    for (int o = 16; o > 0; o >>= 1) {
        s1 += __shfl_xor_sync(0xffffffffu, s1, o);
        s2 += __shfl_xor_sync(0xffffffffu, s2, o);
    }
    __shared__ float sh1[8], sh2[8];
    if (lane == 0) { sh1[wid] = s1; sh2[wid] = s2; }
    __syncthreads();
    float tot1 = 0.f, tot2 = 0.f;
    #pragma unroll
    for (int i = 0; i < 8; i++) { tot1 += sh1[i]; tot2 += sh2[i]; }
    float mu  = tot1 * (1.0f / HH);
    float var = tot2 * (1.0f / HH) - mu * mu;
    float rstd = rsqrtf(var + LN_EPS);
    out[(long long)row * HH + t] = (x - mu) * rstd * gamma[t] + beta[t];
}

// ---------------- launcher ----------------
extern "C" void kernel_launch(void* const* d_in, const int* in_sizes, int n_in,
                              void* d_out, int out_size)
{
    const float* source = (const float*)d_in[0];
    const float* target = (const float*)d_in[1];
    const void*  ei     = d_in[2];

    // The 10 parameter tensors (W0,b0,W1,b1,W2,b2,W3,b3,gamma,beta) are
    // always the LAST 10 inputs; dim_size may or may not be materialized
    // between edge_index and W0. n_in makes this unambiguous.
    const int w = n_in - 10;
    const float* W0 = (const float*)d_in[w + 0];
    const float* b0 = (const float*)d_in[w + 1];
    const float* W1 = (const float*)d_in[w + 2];
    const float* b1 = (const float*)d_in[w + 3];
    const float* W2 = (const float*)d_in[w + 4];
    const float* b2 = (const float*)d_in[w + 5];
    const float* W3 = (const float*)d_in[w + 6];
    const float* b3 = (const float*)d_in[w + 7];
    const float* gamma = (const float*)d_in[w + 8];
    const float* beta  = (const float*)d_in[w + 9];
    float* out = (float*)d_out;

    const int M = in_sizes[0] / HH;      // 50000
    const int E = in_sizes[2] / 2;       // 320000

    float *msg1, *msg2, *agg, *cnt, *comb, *c1, *c2;
    cudaGetSymbolAddress((void**)&msg1, g_msg1);
    cudaGetSymbolAddress((void**)&msg2, g_msg2);
    cudaGetSymbolAddress((void**)&agg,  g_agg);
    cudaGetSymbolAddress((void**)&cnt,  g_cnt);
    cudaGetSymbolAddress((void**)&comb, g_comb);
    cudaGetSymbolAddress((void**)&c1,   g_c1);
    cudaGetSymbolAddress((void**)&c2,   g_c2);

    dim3 gemm_grid(HH / BN, (M + BM - 1) / BM);

    // 0: detect edge_index dtype (int64 vs int32)
    detect_idx_kernel<<<1, 32>>>(ei, E, M);

    // 1-2: message MLP
    sgemm_bias_gelu<<<gemm_grid, 256>>>(source, W0, b0, msg1, M, HH, HH);
    sgemm_bias_gelu<<<gemm_grid, 256>>>(msg1,   W1, b1, msg2, M, HH, HH);

    // 3: zero accumulators
    {
        long long tot = (long long)M * HH / 4 + M;
        int grid = (int)((tot + 255) / 256);
        zero_kernel<<<grid, 256>>>(agg, cnt, M);
    }

    // 4: per-edge scatter (one warp per edge)
    {
        int warps_per_block = 8;
        int grid = (E + warps_per_block - 1) / warps_per_block;
        scatter_kernel<<<grid, 256>>>(msg2, ei, agg, cnt, E);
    }

    // 5: combined = [target || agg/max(cnt,1)]
    {
        long long tot = (long long)M * HH / 4;
        int grid = (int)((tot + 255) / 256);
        combine_kernel<<<grid, 256>>>(target, agg, cnt, comb, M);
    }

    // 6-7: combine MLP
    sgemm_bias_gelu<<<gemm_grid, 256>>>(comb, W2, b2, c1, M, HH, 2 * HH);
    sgemm_bias_gelu<<<gemm_grid, 256>>>(c1,   W3, b3, c2, M, HH, HH);

    // 8: residual + layernorm
    ln_kernel<<<M, 256>>>(c2, target, gamma, beta, out, M);
}

// round 5
// speedup vs baseline: 1.7027x; 1.7027x over previous
#include <cuda_runtime.h>
#include <cuda_bf16.h>
#include <math.h>
#include <stdint.h>

// Problem constants
#define HH 256
#define NN 50000
#define LN_EPS 1e-5f

// ---------------- scratch (no allocations allowed) ----------------
__device__ float g_msg1[(size_t)NN * HH];
__device__ float g_msg2[(size_t)NN * HH];
__device__ float g_agg [(size_t)NN * HH];
__device__ float g_cnt [NN];
__device__ float g_c1  [(size_t)NN * HH];
__device__ float g_c2  [(size_t)NN * HH];
__device__ int   g_idx_is64;

// Pre-split bf16 weights, [n][k] layout. Sections: W0 @0, W1 @65536,
// W3 @131072, W2 @196608 (256*512). 327680 bf16 = 40960 uint4.
__device__ uint4 g_whi4[40960];
__device__ uint4 g_wlo4[40960];

__device__ __forceinline__ float gelu_exact(float x) {
    return 0.5f * x * (1.0f + erff(x * 0.7071067811865476f));
}

// ---------------- weight pre-split: W[k][n] fp32 -> Whi/Wlo[n][k] bf16 ----------------
__global__ void wsplit_kernel(const float* __restrict__ W, int Kw, int off)
{
    __nv_bfloat16* whi = (__nv_bfloat16*)g_whi4;
    __nv_bfloat16* wlo = (__nv_bfloat16*)g_wlo4;
    int i = blockIdx.x * blockDim.x + threadIdx.x;   // i = n*Kw + k
    int total = 256 * Kw;
    if (i >= total) return;
    int n = i / Kw, k = i % Kw;
    float x = W[(long long)k * 256 + n];
    __nv_bfloat16 h = __float2bfloat16_rn(x);
    __nv_bfloat16 l = __float2bfloat16_rn(x - __bfloat162float(h));
    whi[off + i] = h;
    wlo[off + i] = l;
}

// ================= HMMA GEMM: C = epi(A @ W + bias) =================
// CTA tile 128x128, BK=32. 8 warps = 2(m) x 4(n), warp tile 64x32.
// Split product: D += Ahi*Bhi + Ahi*Blo + Alo*Bhi.
#define PADK 40   // 32 + 8 pad; row stride 20 b32 -> conflict-free

__device__ __forceinline__ void mma_bf16(float c[4], uint32_t a0, uint32_t a1,
                                         uint32_t a2, uint32_t a3,
                                         uint32_t b0, uint32_t b1) {
    asm volatile("mma.sync.aligned.m16n8k16.row.col.f32.bf16.bf16.f32 "
                 "{%0,%1,%2,%3}, {%4,%5,%6,%7}, {%8,%9}, {%0,%1,%2,%3};"
                 : "+f"(c[0]), "+f"(c[1]), "+f"(c[2]), "+f"(c[3])
                 : "r"(a0), "r"(a1), "r"(a2), "r"(a3), "r"(b0), "r"(b1));
}

__global__ void __launch_bounds__(256, 2)
gemm_mma(const float* __restrict__ A, const float* __restrict__ A2,
         const float* __restrict__ cnt,
         const __nv_bfloat16* __restrict__ Whi, const __nv_bfloat16* __restrict__ Wlo,
         const float* __restrict__ bias, const float* __restrict__ resid,
         float* __restrict__ C, int M, int K)
{
    __shared__ __nv_bfloat16 sAh[128][PADK];
    __shared__ __nv_bfloat16 sAl[128][PADK];
    __shared__ __nv_bfloat16 sBh[128][PADK];
    __shared__ __nv_bfloat16 sBl[128][PADK];

    const int tid  = threadIdx.x;
    const int wid  = tid >> 5;
    const int lane = tid & 31;
    const int gid  = lane >> 2;
    const int tig  = lane & 3;
    const int wm   = wid >> 2;
    const int wn   = wid & 3;
    const int n0   = blockIdx.x * 128;
    const int m0   = blockIdx.y * 128;

    float acc[4][4][4];
    #pragma unroll
    for (int i = 0; i < 4; i++)
        #pragma unroll
        for (int j = 0; j < 4; j++)
            #pragma unroll
            for (int r = 0; r < 4; r++) acc[i][j][r] = 0.f;

    for (int kc = 0; kc < K; kc += 32) {
        // ---- A chunk: 128 rows x 32 cols fp32 -> hi/lo bf16 ----
        {
            const float* Asrc;
            int koff;
            bool scale = false;
            if (A2 && kc >= 256) { Asrc = A2; koff = kc - 256; scale = true; }
            else                 { Asrc = A;  koff = kc; }
            const int astride = A2 ? 256 : K;
            #pragma unroll
            for (int i = tid; i < 128 * 8; i += 256) {
                const int m = i >> 3;
                const int q = i & 7;
                const int gr = m0 + m;
                float4 v = make_float4(0.f, 0.f, 0.f, 0.f);
                if (gr < M) {
                    v = *(const float4*)(Asrc + (long long)gr * astride + koff + q * 4);
                    if (scale) {
                        const float inv = 1.0f / fmaxf(cnt[gr], 1.0f);
                        v.x *= inv; v.y *= inv; v.z *= inv; v.w *= inv;
                    }
                }
                __nv_bfloat16 h0 = __float2bfloat16_rn(v.x), h1 = __float2bfloat16_rn(v.y);
                __nv_bfloat16 h2 = __float2bfloat16_rn(v.z), h3 = __float2bfloat16_rn(v.w);
                __nv_bfloat16 l0 = __float2bfloat16_rn(v.x - __bfloat162float(h0));
                __nv_bfloat16 l1 = __float2bfloat16_rn(v.y - __bfloat162float(h1));
                __nv_bfloat16 l2 = __float2bfloat16_rn(v.z - __bfloat162float(h2));
                __nv_bfloat16 l3 = __float2bfloat16_rn(v.w - __bfloat162float(h3));
                *(__nv_bfloat162*)&sAh[m][q * 4]     = __halves2bfloat162(h0, h1);
                *(__nv_bfloat162*)&sAh[m][q * 4 + 2] = __halves2bfloat162(h2, h3);
                *(__nv_bfloat162*)&sAl[m][q * 4]     = __halves2bfloat162(l0, l1);
                *(__nv_bfloat162*)&sAl[m][q * 4 + 2] = __halves2bfloat162(l2, l3);
            }
        }
        // ---- B chunk: copy pre-split bf16 [n0..n0+127][kc..kc+31] ----
        #pragma unroll
        for (int i = tid; i < 128 * 4; i += 256) {
            const int n = i >> 2;
            const int seg = i & 3;
            const long long goff = (long long)(n0 + n) * K + kc + seg * 8;
            const uint4 vh = *(const uint4*)(Whi + goff);
            const uint4 vl = *(const uint4*)(Wlo + goff);
            *(uint4*)&sBh[n][seg * 8] = vh;
            *(uint4*)&sBl[n][seg * 8] = vl;
        }
        __syncthreads();

        #pragma unroll
        for (int ks = 0; ks < 2; ks++) {
            uint32_t aa[4][4], bb[4][2];
            const int kb = ks * 8;
            #pragma unroll
            for (int mt = 0; mt < 4; mt++) {
                const int r = wm * 64 + mt * 16 + gid;
                const uint32_t* p0 = (const uint32_t*)&sAh[r][0];
                const uint32_t* p1 = (const uint32_t*)&sAh[r + 8][0];
                aa[mt][0] = p0[kb + tig];
                aa[mt][1] = p1[kb + tig];
                aa[mt][2] = p0[kb + tig + 4];
                aa[mt][3] = p1[kb + tig + 4];
            }
            #pragma unroll
            for (int nt = 0; nt < 4; nt++) {
                const uint32_t* p = (const uint32_t*)&sBh[wn * 32 + nt * 8 + gid][0];
                bb[nt][0] = p[kb + tig];
                bb[nt][1] = p[kb + tig + 4];
            }
            #pragma unroll
            for (int mt = 0; mt < 4; mt++)
                #pragma unroll
                for (int nt = 0; nt < 4; nt++)
                    mma_bf16(acc[mt][nt], aa[mt][0], aa[mt][1], aa[mt][2], aa[mt][3],
                             bb[nt][0], bb[nt][1]);
            #pragma unroll
            for (int nt = 0; nt < 4; nt++) {
                const uint32_t* p = (const uint32_t*)&sBl[wn * 32 + nt * 8 + gid][0];
                bb[nt][0] = p[kb + tig];
                bb[nt][1] = p[kb + tig + 4];
            }
            #pragma unroll
            for (int mt = 0; mt < 4; mt++)
                #pragma unroll
                for (int nt = 0; nt < 4; nt++)
                    mma_bf16(acc[mt][nt], aa[mt][0], aa[mt][1], aa[mt][2], aa[mt][3],
                             bb[nt][0], bb[nt][1]);
            #pragma unroll
            for (int mt = 0; mt < 4; mt++) {
                const int r = wm * 64 + mt * 16 + gid;
                const uint32_t* p0 = (const uint32_t*)&sAl[r][0];
                const uint32_t* p1 = (const uint32_t*)&sAl[r + 8][0];
                aa[mt][0] = p0[kb + tig];
                aa[mt][1] = p1[kb + tig];
                aa[mt][2] = p0[kb + tig + 4];
                aa[mt][3] = p1[kb + tig + 4];
            }
            #pragma unroll
            for (int nt = 0; nt < 4; nt++) {
                const uint32_t* p = (const uint32_t*)&sBh[wn * 32 + nt * 8 + gid][0];
                bb[nt][0] = p[kb + tig];
                bb[nt][1] = p[kb + tig + 4];
            }
            #pragma unroll
            for (int mt = 0; mt < 4; mt++)
                #pragma unroll
                for (int nt = 0; nt < 4; nt++)
                    mma_bf16(acc[mt][nt], aa[mt][0], aa[mt][1], aa[mt][2], aa[mt][3],
                             bb[nt][0], bb[nt][1]);
        }
        __syncthreads();
    }

    // ---- epilogue: bias + gelu (+resid) from accumulator regs ----
    #pragma unroll
    for (int mt = 0; mt < 4; mt++) {
        const int r0 = m0 + wm * 64 + mt * 16 + gid;
        const int r1 = r0 + 8;
        #pragma unroll
        for (int nt = 0; nt < 4; nt++) {
            const int col = n0 + wn * 32 + nt * 8 + tig * 2;
            const float bv0 = bias[col], bv1 = bias[col + 1];
            if (r0 < M) {
                float2 o;
                o.x = gelu_exact(acc[mt][nt][0] + bv0);
                o.y = gelu_exact(acc[mt][nt][1] + bv1);
                if (resid) {
                    const float2 t = *(const float2*)(resid + (long long)r0 * 256 + col);
                    o.x += t.x; o.y += t.y;
                }
                *(float2*)(C + (long long)r0 * 256 + col) = o;
            }
            if (r1 < M) {
                float2 o;
                o.x = gelu_exact(acc[mt][nt][2] + bv0);
                o.y = gelu_exact(acc[mt][nt][3] + bv1);
                if (resid) {
                    const float2 t = *(const float2*)(resid + (long long)r1 * 256 + col);
                    o.x += t.x; o.y += t.y;
                }
                *(float2*)(C + (long long)r1 * 256 + col) = o;
            }
        }
    }
}

// ---------------- index-dtype detection ----------------
__global__ void detect_idx_kernel(const void* __restrict__ ei, int E, int N)
{
    if (blockIdx.x != 0 || threadIdx.x != 0) return;
    const long long* p = (const long long*)ei;
    int n = E < 64 ? E : 64;
    int ok = 1;
    for (int i = 0; i < n; i++) {
        long long v = p[i];
        if (v < 0 || v >= (long long)N) { ok = 0; break; }
    }
    g_idx_is64 = ok;
}

// ---------------- zero agg + counts ----------------
__global__ void zero_kernel(float* __restrict__ agg, float* __restrict__ cnt, int M)
{
    long long i = (long long)blockIdx.x * blockDim.x + threadIdx.x;
    long long n4 = (long long)M * HH / 4;
    if (i < n4) {
        ((float4*)agg)[i] = make_float4(0.f, 0.f, 0.f, 0.f);
    } else if (i < n4 + M) {
        cnt[i - n4] = 0.f;
    }
}

// ---------------- per-edge scatter ----------------
__global__ void __launch_bounds__(256)
scatter_kernel(const float* __restrict__ msg, const void* __restrict__ ei_raw,
               float* __restrict__ agg, float* __restrict__ cnt, int E)
{
    int warp = (int)((blockIdx.x * (long long)blockDim.x + threadIdx.x) >> 5);
    int lane = threadIdx.x & 31;
    if (warp >= E) return;

    long long src, dst;
    if (g_idx_is64) {
        const long long* p = (const long long*)ei_raw;
        src = p[warp];
        dst = p[(long long)E + warp];
    } else {
        const int* p = (const int*)ei_raw;
        src = p[warp];
        dst = p[E + warp];
    }

    const float4* s = (const float4*)(msg + src * HH);
    float4*       d = (float4*)(agg + dst * HH);
    #pragma unroll
    for (int i = 0; i < 2; i++) {
        float4 v = __ldg(s + lane + 32 * i);
        atomicAdd(d + lane + 32 * i, v);
    }
    if (lane == 0) atomicAdd(cnt + dst, 1.0f);
}

// ---------------- layernorm (input already has residual) ----------------
__global__ void __launch_bounds__(256)
ln_kernel(const float* __restrict__ x_in,
          const float* __restrict__ gamma, const float* __restrict__ beta,
          float* __restrict__ out, int M)
{
    int row = blockIdx.x;
    if (row >= M) return;
    int t = threadIdx.x;
    int lane = t & 31, wid = t >> 5;

    float x = x_in[(long long)row * HH + t];
    float s1 = x, s2 = x * x;
    #pragma unroll
    for (int o = 16; o > 0; o >>= 1) {
        s1 += __shfl_xor_sync(0xffffffffu, s1, o);
        s2 += __shfl_xor_sync(0xffffffffu, s2, o);
    }
    __shared__ float sh1[8], sh2[8];
    if (lane == 0) { sh1[wid] = s1; sh2[wid] = s2; }
    __syncthreads();
    float tot1 = 0.f, tot2 = 0.f;
    #pragma unroll
    for (int i = 0; i < 8; i++) { tot1 += sh1[i]; tot2 += sh2[i]; }
    float mu  = tot1 * (1.0f / HH);
    float var = tot2 * (1.0f / HH) - mu * mu;
    float rstd = rsqrtf(var + LN_EPS);
    out[(long long)row * HH + t] = (x - mu) * rstd * gamma[t] + beta[t];
}

// ---------------- launcher ----------------
extern "C" void kernel_launch(void* const* d_in, const int* in_sizes, int n_in,
                              void* d_out, int out_size)
{
    const float* source = (const float*)d_in[0];
    const float* target = (const float*)d_in[1];
    const void*  ei     = d_in[2];

    const int w = n_in - 10;   // last 10 inputs are the parameter tensors
    const float* W0 = (const float*)d_in[w + 0];
    const float* b0 = (const float*)d_in[w + 1];
    const float* W1 = (const float*)d_in[w + 2];
    const float* b1 = (const float*)d_in[w + 3];
    const float* W2 = (const float*)d_in[w + 4];
    const float* b2 = (const float*)d_in[w + 5];
    const float* W3 = (const float*)d_in[w + 6];
    const float* b3 = (const float*)d_in[w + 7];
    const float* gamma = (const float*)d_in[w + 8];
    const float* beta  = (const float*)d_in[w + 9];
    float* out = (float*)d_out;

    const int M = in_sizes[0] / HH;      // 50000
    const int E = in_sizes[2] / 2;       // 320000

    float *msg1, *msg2, *agg, *cnt, *c1, *c2;
    cudaGetSymbolAddress((void**)&msg1, g_msg1);
    cudaGetSymbolAddress((void**)&msg2, g_msg2);
    cudaGetSymbolAddress((void**)&agg,  g_agg);
    cudaGetSymbolAddress((void**)&cnt,  g_cnt);
    cudaGetSymbolAddress((void**)&c1,   g_c1);
    cudaGetSymbolAddress((void**)&c2,   g_c2);
    uint4 *whi4, *wlo4;
    cudaGetSymbolAddress((void**)&whi4, g_whi4);
    cudaGetSymbolAddress((void**)&wlo4, g_wlo4);
    const __nv_bfloat16* whi = (const __nv_bfloat16*)whi4;
    const __nv_bfloat16* wlo = (const __nv_bfloat16*)wlo4;

    const int mtiles = (M + 127) / 128;
    dim3 ggrid(2, mtiles);

    // 0: detect edge_index dtype; pre-split weights to bf16 hi/lo
    detect_idx_kernel<<<1, 32>>>(ei, E, M);
    wsplit_kernel<<<(256 * 256 + 255) / 256, 256>>>(W0, 256, 0);
    wsplit_kernel<<<(256 * 256 + 255) / 256, 256>>>(W1, 256, 65536);
    wsplit_kernel<<<(256 * 256 + 255) / 256, 256>>>(W3, 256, 131072);
    wsplit_kernel<<<(256 * 512 + 255) / 256, 256>>>(W2, 512, 196608);

    // 1-2: message MLP (tensor cores via mma.sync)
    gemm_mma<<<ggrid, 256>>>(source, nullptr, nullptr, whi, wlo, b0, nullptr, msg1, M, 256);
    gemm_mma<<<ggrid, 256>>>(msg1, nullptr, nullptr, whi + 65536, wlo + 65536, b1, nullptr, msg2, M, 256);

    // 3: zero accumulators
    {
        long long tot = (long long)M * HH / 4 + M;
        int grid = (int)((tot + 255) / 256);
        zero_kernel<<<grid, 256>>>(agg, cnt, M);
    }

    // 4: per-edge scatter (one warp per edge)
    {
        int grid = (E + 7) / 8;
        scatter_kernel<<<grid, 256>>>(msg2, ei, agg, cnt, E);
    }

    // 5: combine GEMM with fused concat [target || agg/max(cnt,1)], K=512
    gemm_mma<<<ggrid, 256>>>(target, agg, cnt, whi + 196608, wlo + 196608, b2, nullptr, c1, M, 512);

    // 6: final GEMM with fused residual add (c2 = gelu(c1@W3+b3) + target)
    gemm_mma<<<ggrid, 256>>>(c1, nullptr, nullptr, whi + 131072, wlo + 131072, b3, target, c2, M, 256);

    // 7: layernorm
    ln_kernel<<<M, 256>>>(c2, gamma, beta, out, M);
}